// round 14
// baseline (speedup 1.0000x reference)
#include <cuda_runtime.h>
#include <cuda_fp16.h>
#include <cstdint>

// Problem dims
#define MDIM 8192   // B*S
#define NDIM 4096
#define KDIM 4096
#define K16  (KDIM / 16)      // 256

// GEMM tiling: 128x128 CTA, 8 warps (4m x 2n), warp tile 32x64
#define TM 128
#define TN 128
#define KC 64                 // k64 chunk = 4 k16 steps
#define NK (KDIM / KC)        // 64
#define NSTAGE 4              // B-only stages
#define B_STAGE 16384         // 2 n64-blocks x 4 k16 x 2048B
#define SMEM_DYN (NSTAGE * B_STAGE)          // 65536

// Pre-pass grid split (256-thread blocks, 8 warps each)
#define ACONV_BLOCKS ((MDIM / 16) * K16 / 8)        // 16384
#define DEQ_BLOCKS   ((NDIM / 64) * K16 / 8)        // 2048

// Fragment-layout scratch (allocation-free rule: __device__ globals)
// A: per (m16, k16) tile: 512B block, lane l owns bytes [16l,16l+16) = a0..a3
__device__ uint4 g_Afrag[(MDIM / 16) * (size_t)K16 * 32];
// W: per (n64, k16) block: 2KB; uint4 j*32+l = frags (2j, 2j+1) for lane l
__device__ uint4 g_Wfrag[(NDIM / 64) * (size_t)K16 * 128];

// ---------------------------------------------------------------------------
__device__ __forceinline__ uint32_t smem_u32(const void* p) {
    uint32_t r;
    asm("{ .reg .u64 t; cvta.to.shared.u64 t, %1; cvt.u32.u64 %0, t; }"
        : "=r"(r) : "l"(p));
    return r;
}

__device__ __forceinline__ void cp_async16(uint32_t s, const void* g) {
    asm volatile("cp.async.cg.shared.global [%0], [%1], 16;"
                 :: "r"(s), "l"(__cvta_generic_to_global(g)) : "memory");
}

#define LDS128(v, addr)                                                        \
    asm volatile("ld.shared.v4.b32 {%0,%1,%2,%3}, [%4];"                       \
                 : "=r"((v).x), "=r"((v).y), "=r"((v).z), "=r"((v).w)          \
                 : "r"(addr))

__device__ __forceinline__ void mma16816(float* d, const uint32_t* a,
                                         const uint32_t* b) {
    asm volatile(
        "mma.sync.aligned.m16n8k16.row.col.f32.f16.f16.f32 "
        "{%0,%1,%2,%3}, {%4,%5,%6,%7}, {%8,%9}, {%0,%1,%2,%3};"
        : "+f"(d[0]), "+f"(d[1]), "+f"(d[2]), "+f"(d[3])
        : "r"(a[0]), "r"(a[1]), "r"(a[2]), "r"(a[3]), "r"(b[0]), "r"(b[1]));
}

__device__ __forceinline__ uint32_t pack_h2(float x, float y) {
    __half2 h = __floats2half2_rn(x, y);
    return *(uint32_t*)&h;
}

// ---------------------------------------------------------------------------
// Merged pre-pass (identical to R12 — proven numerics + throughput).
// ---------------------------------------------------------------------------
__global__ void __launch_bounds__(256)
k_pre(const float* __restrict__ in, const int* __restrict__ qw,
      const float* __restrict__ sc, const int* __restrict__ qz) {
    const int l = threadIdx.x & 31;
    if (blockIdx.x < ACONV_BLOCKS) {
        int w = (blockIdx.x << 3) | (threadIdx.x >> 5);
        int k16 = w & (K16 - 1);
        int m16 = w >> 8;
        int m = (m16 << 4) + (l >> 2);
        int k = (k16 << 4) + 2 * (l & 3);
        const float* p = in + (size_t)m * KDIM + k;
        float2 f0 = *(const float2*)(p);
        float2 f1 = *(const float2*)(p + 8 * KDIM);
        float2 f2 = *(const float2*)(p + 8);
        float2 f3 = *(const float2*)(p + 8 * KDIM + 8);
        uint4 o;
        o.x = pack_h2(f0.x, f0.y);
        o.y = pack_h2(f1.x, f1.y);
        o.z = pack_h2(f2.x, f2.y);
        o.w = pack_h2(f3.x, f3.y);
        g_Afrag[((size_t)m16 * K16 + k16) * 32 + l] = o;
    } else {
        int w = ((blockIdx.x - ACONV_BLOCKS) << 3) | (threadIdx.x >> 5);
        int k16 = w & (K16 - 1);
        int n64 = w >> 8;                 // 0..63
        int nb = n64 << 6;
        int g   = k16 >> 3;               // group = k/128
        int kk0 = k16 << 1;               // q row for k 0..7 of this tile
        int sh  = (l & 3) << 3;           // nibble-pair start bit
        uint4 ov[4];
#pragma unroll
        for (int j = 0; j < 4; ++j) {
            uint32_t r[4];
#pragma unroll
            for (int h = 0; h < 2; ++h) {
                int f = 2 * j + h;
                int n = nb + f * 8 + (l >> 2);
                uint32_t q0 = (uint32_t)qw[(size_t)kk0 * NDIM + n];
                uint32_t q1 = (uint32_t)qw[(size_t)(kk0 + 1) * NDIM + n];
                float s = sc[(size_t)g * NDIM + n];
                int zw = qz[g * (NDIM / 8) + (n >> 3)];
                float z = (float)((zw >> ((n & 7) << 2)) & 15);
                float w00 = ((float)((q0 >> sh) & 15) - z) * s;
                float w01 = ((float)((q0 >> (sh + 4)) & 15) - z) * s;
                float w10 = ((float)((q1 >> sh) & 15) - z) * s;
                float w11 = ((float)((q1 >> (sh + 4)) & 15) - z) * s;
                r[2 * h]     = pack_h2(w00, w01);   // reg0 (k 0-7)
                r[2 * h + 1] = pack_h2(w10, w11);   // reg1 (k 8-15)
            }
            ov[j].x = r[0]; ov[j].y = r[1]; ov[j].z = r[2]; ov[j].w = r[3];
        }
        uint4* dst = g_Wfrag + ((size_t)n64 * K16 + k16) * 128 + l;
#pragma unroll
        for (int j = 0; j < 4; ++j) dst[j * 32] = ov[j];
    }
}

// ---------------------------------------------------------------------------
// Main GEMM: C = A @ W^T + bias + residual.
// A: direct fragment LDG.128, full-step-ahead register ping-pong (off the
// smem crossbar entirely). B: 4-stage fragment-smem ring (cp.async linear
// copies -> ld.shared.v4), pointer-rotation slot ring, cp.async pairs
// interleaved between MMA groups, barrier at iter end + next-chunk preload.
// ---------------------------------------------------------------------------
__global__ void __launch_bounds__(256, 2)
k_gemm(const float* __restrict__ residual, const float* __restrict__ bias,
       float* __restrict__ out) {
    extern __shared__ char smem_raw[];
    const uint32_t sbase = smem_u32(smem_raw);

    const int tid  = threadIdx.x;
    const int wid  = tid >> 5;
    const int lane = tid & 31;
    const int warp_m = wid & 3;   // 4 warps along M (32 rows)
    const int warp_n = wid >> 2;  // 2 warps along N (64 cols)

    // L2-friendly raster: supertiles of 8 m-tiles x 32 n-tiles
    const int bid = blockIdx.x;
    const int tm_ = ((bid >> 8) << 3) | (bid & 7);
    const int tn_ = (bid >> 3) & 31;

    // A: fragment pointers (two m16 rows per warp), step stride 32 uint4
    const int m16idx0 = tm_ * 8 + warp_m * 2;
    const uint4* pA0 = g_Afrag + (size_t)m16idx0 * K16 * 32 + lane;
    const uint4* pA1 = pA0 + (size_t)K16 * 32;

    // B: global fragment panel, chunk stride 512 uint4 per n64-block.
    // Prologue loads chunks 0..2; mainloop iter i loads chunk i+3.
    const uint4* gW = g_Wfrag + (size_t)(tn_ * 2) * K16 * 128;
    const uint4* pBc = gW + tid + 3 * 512;          // chunk 3 onward (FIX)
    const uint32_t bdst = (uint32_t)(tid * 16);

    // Compute-side B read base: + s*2048 + j*512
    const uint32_t bRd = (uint32_t)(warp_n * 8192 + lane * 16);

    float acc[2][8][4];
#pragma unroll
    for (int mt = 0; mt < 2; ++mt)
#pragma unroll
        for (int f = 0; f < 8; ++f)
#pragma unroll
            for (int j = 0; j < 4; ++j) acc[mt][f][j] = 0.f;

#define LOAD_BV(bb, sB_, s)                                                    \
    do {                                                                       \
        LDS128((bb)[0], (sB_) + (s) * 2048);                                   \
        LDS128((bb)[1], (sB_) + (s) * 2048 + 512);                             \
        LDS128((bb)[2], (sB_) + (s) * 2048 + 1024);                            \
        LDS128((bb)[3], (sB_) + (s) * 2048 + 1536);                            \
    } while (0)

#define MMA_MT(mt, Areg, bb)                                                   \
    do {                                                                       \
        const uint32_t* ar = (const uint32_t*)&(Areg);                         \
        _Pragma("unroll")                                                      \
        for (int nt = 0; nt < 4; ++nt) {                                       \
            const uint32_t* br = (const uint32_t*)&(bb)[nt];                   \
            mma16816(acc[mt][2 * nt],     ar, br);                             \
            mma16816(acc[mt][2 * nt + 1], ar, br + 2);                         \
        }                                                                      \
    } while (0)

    // B full-chunk load (prologue): 4 x 16B per thread
    auto load_B = [&](int c, uint32_t sdst) {
        const uint4* p = gW + tid + (size_t)c * 512;
        cp_async16(sdst + bdst,         p);
        cp_async16(sdst + bdst + 4096,  p + 256);
        cp_async16(sdst + bdst + 8192,  p + 32768);
        cp_async16(sdst + bdst + 12288, p + 33024);
    };

    load_B(0, sbase);
    asm volatile("cp.async.commit_group;" ::: "memory");
    load_B(1, sbase + B_STAGE);
    asm volatile("cp.async.commit_group;" ::: "memory");
    load_B(2, sbase + 2 * B_STAGE);
    asm volatile("cp.async.commit_group;" ::: "memory");
    asm volatile("cp.async.wait_group 2;" ::: "memory");
    __syncthreads();

    // 4-slot ring: s0 = slot(i), s1 = slot(i+1), s3 = dst slot(i+3)
    uint32_t s0 = sbase;
    uint32_t s1 = sbase + B_STAGE;
    uint32_t s2 = sbase + 2 * B_STAGE;
    uint32_t s3 = sbase + 3 * B_STAGE;

    uint4 Av0[2], Av1[2], Bv0[4], Bv1[4];
    LOAD_BV(Bv0, s0 + bRd, 0);
    Av0[0] = __ldg(pA0);
    Av0[1] = __ldg(pA1);

#pragma unroll 1
    for (int i = 0; i < NK; ++i) {
        const uint32_t sBc = s0 + bRd;
        const bool ld = (i + 3 < NK);

        // ---- step 0 (Bv0, Av0) ----
        LOAD_BV(Bv1, sBc, 1);
        Av1[0] = __ldg(pA0 + 32);
        Av1[1] = __ldg(pA1 + 32);
        if (ld) {
            cp_async16(s3 + bdst,        pBc);
            cp_async16(s3 + bdst + 4096, pBc + 256);
        }
        MMA_MT(0, Av0[0], Bv0);
        MMA_MT(1, Av0[1], Bv0);

        // ---- step 1 (Bv1, Av1) ----
        LOAD_BV(Bv0, sBc, 2);
        Av0[0] = __ldg(pA0 + 64);
        Av0[1] = __ldg(pA1 + 64);
        if (ld) {
            cp_async16(s3 + bdst + 8192,  pBc + 32768);
            cp_async16(s3 + bdst + 12288, pBc + 33024);
        }
        MMA_MT(0, Av1[0], Bv1);
        MMA_MT(1, Av1[1], Bv1);
        asm volatile("cp.async.commit_group;" ::: "memory");

        // ---- step 2 (Bv0, Av0) ----
        LOAD_BV(Bv1, sBc, 3);
        Av1[0] = __ldg(pA0 + 96);
        Av1[1] = __ldg(pA1 + 96);
        MMA_MT(0, Av0[0], Bv0);
        MMA_MT(1, Av0[1], Bv0);

        // ---- step 3 (Bv1, Av1) ----
        MMA_MT(0, Av1[0], Bv1);
        MMA_MT(1, Av1[1], Bv1);

        pA0 += 128;
        pA1 += 128;
        pBc += 512;

        // barrier: afterwards chunk i+1 resident (<=2 groups pending)
        asm volatile("cp.async.wait_group 2;" ::: "memory");
        __syncthreads();

        // preload step-0 state of chunk i+1
        if (i + 1 < NK) {
            LOAD_BV(Bv0, s1 + bRd, 0);
            Av0[0] = __ldg(pA0);
            Av0[1] = __ldg(pA1);
        }

        // rotate 4-slot ring
        uint32_t t = s0;
        s0 = s1; s1 = s2; s2 = s3; s3 = t;
    }

    // Epilogue: fp32 acc + bias + residual -> out
    const int r  = lane >> 2;
    const int c2 = (lane & 3) * 2;
    const int mbase = tm_ * TM + warp_m * 32;
    const int nbase = tn_ * TN + warp_n * 64;
#pragma unroll
    for (int mt = 0; mt < 2; ++mt) {
#pragma unroll
        for (int half = 0; half < 2; ++half) {   // rows r and r+8
            const size_t m = (size_t)(mbase + mt * 16 + r + half * 8);
            const float* rp = residual + m * NDIM + nbase;
            float* op = out + m * NDIM + nbase;
#pragma unroll
            for (int f = 0; f < 8; ++f) {
                const int n = f * 8 + c2;
                float2 res = *(const float2*)(rp + n);
                float2 bz  = *(const float2*)(bias + nbase + n);
                float2 o;
                o.x = acc[mt][f][2 * half]     + bz.x + res.x;
                o.y = acc[mt][f][2 * half + 1] + bz.y + res.y;
                *(float2*)(op + n) = o;
            }
        }
    }
}

// ---------------------------------------------------------------------------
extern "C" void kernel_launch(void* const* d_in, const int* in_sizes, int n_in,
                              void* d_out, int out_size) {
    const float* input    = (const float*)d_in[0];   // [2,4096,4096] f32
    const float* residual = (const float*)d_in[1];   // [2,4096,4096] f32
    const int*   qweight  = (const int*)d_in[2];     // [512,4096] i32
    const float* scales   = (const float*)d_in[3];   // [32,4096] f32
    const int*   qzeros   = (const int*)d_in[4];     // [32,512] i32
    const float* bias     = (const float*)d_in[5];   // [4096] f32
    float* out = (float*)d_out;

    cudaFuncSetAttribute(k_gemm, cudaFuncAttributeMaxDynamicSharedMemorySize,
                         SMEM_DYN);

    k_pre<<<ACONV_BLOCKS + DEQ_BLOCKS, 256>>>(input, qweight, scales, qzeros);

    const int nblocks = (MDIM / TM) * (NDIM / TN);   // 2048
    k_gemm<<<nblocks, 256, SMEM_DYN>>>(residual, bias, out);
}

// round 15
// speedup vs baseline: 1.1670x; 1.1670x over previous
#include <cuda_runtime.h>
#include <cuda_fp16.h>
#include <cstdint>

// Problem dims
#define MDIM 8192   // B*S
#define NDIM 4096
#define KDIM 4096
#define K16  (KDIM / 16)      // 256

// GEMM tiling: 128x128 CTA, 8 warps (4m x 2n), warp tile 32x64
#define TM 128
#define TN 128
#define KC 32                 // k32 chunk = 2 k16 steps
#define NK2 (KDIM / KC)       // 128
#define NSLOT 6
#define SLOT_BYTES 16384      // A 8KB + B 8KB
#define SMEM_DYN (NSLOT * SLOT_BYTES)        // 98304

// Pre-pass grid split (256-thread blocks, 8 warps each)
#define ACONV_BLOCKS ((MDIM / 16) * K16 / 8)        // 16384
#define DEQ_BLOCKS   ((NDIM / 64) * K16 / 8)        // 2048

// Fragment-layout scratch (allocation-free rule: __device__ globals)
// A: per (m16, k16) tile: 512B block, lane l owns bytes [16l,16l+16) = a0..a3
__device__ uint4 g_Afrag[(MDIM / 16) * (size_t)K16 * 32];
// W: per (n64, k16) block: 2KB; uint4 j*32+l = frags (2j, 2j+1) for lane l
__device__ uint4 g_Wfrag[(NDIM / 64) * (size_t)K16 * 128];

// ---------------------------------------------------------------------------
__device__ __forceinline__ uint32_t smem_u32(const void* p) {
    uint32_t r;
    asm("{ .reg .u64 t; cvta.to.shared.u64 t, %1; cvt.u32.u64 %0, t; }"
        : "=r"(r) : "l"(p));
    return r;
}

__device__ __forceinline__ void cp_async16(uint32_t s, const void* g) {
    asm volatile("cp.async.cg.shared.global [%0], [%1], 16;"
                 :: "r"(s), "l"(__cvta_generic_to_global(g)) : "memory");
}

#define LDS128(v, addr)                                                        \
    asm volatile("ld.shared.v4.b32 {%0,%1,%2,%3}, [%4];"                       \
                 : "=r"((v).x), "=r"((v).y), "=r"((v).z), "=r"((v).w)          \
                 : "r"(addr))

__device__ __forceinline__ void mma16816(float* d, const uint32_t* a,
                                         const uint32_t* b) {
    asm volatile(
        "mma.sync.aligned.m16n8k16.row.col.f32.f16.f16.f32 "
        "{%0,%1,%2,%3}, {%4,%5,%6,%7}, {%8,%9}, {%0,%1,%2,%3};"
        : "+f"(d[0]), "+f"(d[1]), "+f"(d[2]), "+f"(d[3])
        : "r"(a[0]), "r"(a[1]), "r"(a[2]), "r"(a[3]), "r"(b[0]), "r"(b[1]));
}

__device__ __forceinline__ uint32_t pack_h2(float x, float y) {
    __half2 h = __floats2half2_rn(x, y);
    return *(uint32_t*)&h;
}

// ---------------------------------------------------------------------------
// Merged pre-pass (identical to R12 — proven numerics + throughput).
// ---------------------------------------------------------------------------
__global__ void __launch_bounds__(256)
k_pre(const float* __restrict__ in, const int* __restrict__ qw,
      const float* __restrict__ sc, const int* __restrict__ qz) {
    const int l = threadIdx.x & 31;
    if (blockIdx.x < ACONV_BLOCKS) {
        int w = (blockIdx.x << 3) | (threadIdx.x >> 5);
        int k16 = w & (K16 - 1);
        int m16 = w >> 8;
        int m = (m16 << 4) + (l >> 2);
        int k = (k16 << 4) + 2 * (l & 3);
        const float* p = in + (size_t)m * KDIM + k;
        float2 f0 = *(const float2*)(p);
        float2 f1 = *(const float2*)(p + 8 * KDIM);
        float2 f2 = *(const float2*)(p + 8);
        float2 f3 = *(const float2*)(p + 8 * KDIM + 8);
        uint4 o;
        o.x = pack_h2(f0.x, f0.y);
        o.y = pack_h2(f1.x, f1.y);
        o.z = pack_h2(f2.x, f2.y);
        o.w = pack_h2(f3.x, f3.y);
        g_Afrag[((size_t)m16 * K16 + k16) * 32 + l] = o;
    } else {
        int w = ((blockIdx.x - ACONV_BLOCKS) << 3) | (threadIdx.x >> 5);
        int k16 = w & (K16 - 1);
        int n64 = w >> 8;                 // 0..63
        int nb = n64 << 6;
        int g   = k16 >> 3;               // group = k/128
        int kk0 = k16 << 1;               // q row for k 0..7 of this tile
        int sh  = (l & 3) << 3;           // nibble-pair start bit
        uint4 ov[4];
#pragma unroll
        for (int j = 0; j < 4; ++j) {
            uint32_t r[4];
#pragma unroll
            for (int h = 0; h < 2; ++h) {
                int f = 2 * j + h;
                int n = nb + f * 8 + (l >> 2);
                uint32_t q0 = (uint32_t)qw[(size_t)kk0 * NDIM + n];
                uint32_t q1 = (uint32_t)qw[(size_t)(kk0 + 1) * NDIM + n];
                float s = sc[(size_t)g * NDIM + n];
                int zw = qz[g * (NDIM / 8) + (n >> 3)];
                float z = (float)((zw >> ((n & 7) << 2)) & 15);
                float w00 = ((float)((q0 >> sh) & 15) - z) * s;
                float w01 = ((float)((q0 >> (sh + 4)) & 15) - z) * s;
                float w10 = ((float)((q1 >> sh) & 15) - z) * s;
                float w11 = ((float)((q1 >> (sh + 4)) & 15) - z) * s;
                r[2 * h]     = pack_h2(w00, w01);   // reg0 (k 0-7)
                r[2 * h + 1] = pack_h2(w10, w11);   // reg1 (k 8-15)
            }
            ov[j].x = r[0]; ov[j].y = r[1]; ov[j].z = r[2]; ov[j].w = r[3];
        }
        uint4* dst = g_Wfrag + ((size_t)n64 * K16 + k16) * 128 + l;
#pragma unroll
        for (int j = 0; j < 4; ++j) dst[j * 32] = ov[j];
    }
}

// ---------------------------------------------------------------------------
// Main GEMM: C = A @ W^T + bias + residual.
// Fragment-layout smem pipeline, KC=32 chunks, 6-slot ring, load distance 4,
// wait_group 2 at iter end => chunk i+1 is resident+visible one FULL
// iteration before use, so its step-0 fragments are preloaded BEFORE the
// barrier (hidden under step-1 MMAs). Post-barrier opens directly with MMAs.
// ---------------------------------------------------------------------------
__global__ void __launch_bounds__(256, 2)
k_gemm(const float* __restrict__ residual, const float* __restrict__ bias,
       float* __restrict__ out) {
    extern __shared__ char smem_raw[];
    const uint32_t sbase = smem_u32(smem_raw);

    const int tid  = threadIdx.x;
    const int wid  = tid >> 5;
    const int lane = tid & 31;
    const int warp_m = wid & 3;   // 4 warps along M (32 rows)
    const int warp_n = wid >> 2;  // 2 warps along N (64 cols)

    // L2-friendly raster: supertiles of 8 m-tiles x 32 n-tiles
    const int bid = blockIdx.x;
    const int tm_ = ((bid >> 8) << 3) | (bid & 7);
    const int tn_ = (bid >> 3) & 31;

    // ---- loader geometry (linear copies, affine in tid) ------------------
    // A slot layout: [m16l 0..7][k16l 0..1][lane] -> 8KB
    // piece p = tid + 256r: m16l = p>>6, k16l = (p>>5)&1, lane = p&31
    // B slot layout at +8192: [n64l 0..1][k16l 0..1][j 0..3][lane] -> 8KB
    const uint4* pA = g_Afrag + (size_t)(tm_ * 8 + (tid >> 6)) * K16 * 32 +
                      ((tid >> 5) & 1) * 32 + (tid & 31);
    const uint4* pB = g_Wfrag + (size_t)(tn_ * 2) * K16 * 128 +
                      ((tid >> 7) & 1) * 128 + (tid & 127);
    const uint32_t adst = (uint32_t)(tid * 16);
    const uint32_t bdst = (uint32_t)(8192 + tid * 16);
    // r=1 constant source offsets (in uint4)
    const size_t aoff1 = (size_t)4 * K16 * 32;
    const size_t boff1 = (size_t)K16 * 128;

    // ---- compute-side read bases -----------------------------------------
    const uint32_t a0off = (uint32_t)((warp_m * 2) * 1024 + lane * 16);
    const uint32_t a1off = a0off + 1024;
    const uint32_t bRd   = (uint32_t)(8192 + warp_n * 4096 + lane * 16);

    float acc[2][8][4];
#pragma unroll
    for (int mt = 0; mt < 2; ++mt)
#pragma unroll
        for (int f = 0; f < 8; ++f)
#pragma unroll
            for (int j = 0; j < 4; ++j) acc[mt][f][j] = 0.f;

#define LOAD_BV(bb, base_)                                                     \
    do {                                                                       \
        LDS128((bb)[0], (base_));                                              \
        LDS128((bb)[1], (base_) + 512);                                        \
        LDS128((bb)[2], (base_) + 1024);                                       \
        LDS128((bb)[3], (base_) + 1536);                                       \
    } while (0)

#define MMA_MT(mt, Areg, bb)                                                   \
    do {                                                                       \
        const uint32_t* ar = (const uint32_t*)&(Areg);                         \
        _Pragma("unroll")                                                      \
        for (int nt = 0; nt < 4; ++nt) {                                       \
            const uint32_t* br = (const uint32_t*)&(bb)[nt];                   \
            mma16816(acc[mt][2 * nt],     ar, br);                             \
            mma16816(acc[mt][2 * nt + 1], ar, br + 2);                         \
        }                                                                      \
    } while (0)

    // ---- prologue: load chunks 0..3 into slots 0..3 ----------------------
#pragma unroll
    for (int c = 0; c < 4; ++c) {
        const uint32_t sd = sbase + c * SLOT_BYTES;
        cp_async16(sd + adst,        pA + (size_t)c * 64);
        cp_async16(sd + adst + 4096, pA + (size_t)c * 64 + aoff1);
        cp_async16(sd + bdst,        pB + (size_t)c * 256);
        cp_async16(sd + bdst + 4096, pB + (size_t)c * 256 + boff1);
        asm volatile("cp.async.commit_group;" ::: "memory");
    }
    asm volatile("cp.async.wait_group 2;" ::: "memory");   // chunks 0,1 done
    __syncthreads();

    // loader pointers advance to chunk 4
    pA += 4 * 64;
    pB += 4 * 256;

    // slot ring: q0 = slot(i), q1 = slot(i+1), q4 = dst slot(i+4)
    uint32_t q0 = sbase;
    uint32_t q1 = sbase + SLOT_BYTES;
    uint32_t q2 = sbase + 2 * SLOT_BYTES;
    uint32_t q3 = sbase + 3 * SLOT_BYTES;
    uint32_t q4 = sbase + 4 * SLOT_BYTES;
    uint32_t q5 = sbase + 5 * SLOT_BYTES;

    uint4 A0, A1, Bv0[4], Bv1[4];
    LOAD_BV(Bv0, q0 + bRd);
    LDS128(A0, q0 + a0off);
    LDS128(A1, q0 + a1off);

#pragma unroll 1
    for (int i = 0; i < NK2; ++i) {
        const bool ld = (i + 4 < NK2);

        // ---- step 0: consume chunk i step 0 (Bv0, A0/A1) ----
        LOAD_BV(Bv1, q0 + bRd + 2048);         // chunk i, step 1
        if (ld) {
            cp_async16(q4 + adst,        pA);
            cp_async16(q4 + adst + 4096, pA + aoff1);
        }
        MMA_MT(0, A0, Bv0);
        LDS128(A0, q0 + a0off + 512);          // chunk i, step 1
        if (ld) {
            cp_async16(q4 + bdst,        pB);
            cp_async16(q4 + bdst + 4096, pB + boff1);
        }
        MMA_MT(1, A1, Bv0);
        LDS128(A1, q0 + a1off + 512);
        asm volatile("cp.async.commit_group;" ::: "memory");

        // ---- step 1: consume chunk i step 1 (Bv1, A0/A1) ----
        // PRE-BARRIER preload of chunk i+1 step 0 (resident since end of
        // iter i-1; made visible by that iteration's barrier).
        LOAD_BV(Bv0, q1 + bRd);
        MMA_MT(0, A0, Bv1);
        LDS128(A0, q1 + a0off);
        MMA_MT(1, A1, Bv1);
        LDS128(A1, q1 + a1off);

        pA += 64;
        pB += 256;

        // barrier: completes chunk i+2; nothing depends on it afterwards
        asm volatile("cp.async.wait_group 2;" ::: "memory");
        __syncthreads();

        // rotate 6-slot ring
        uint32_t t = q0;
        q0 = q1; q1 = q2; q2 = q3; q3 = q4; q4 = q5; q5 = t;
    }

    // Epilogue: fp32 acc + bias + residual -> out
    const int r  = lane >> 2;
    const int c2 = (lane & 3) * 2;
    const int mbase = tm_ * TM + warp_m * 32;
    const int nbase = tn_ * TN + warp_n * 64;
#pragma unroll
    for (int mt = 0; mt < 2; ++mt) {
#pragma unroll
        for (int half = 0; half < 2; ++half) {   // rows r and r+8
            const size_t m = (size_t)(mbase + mt * 16 + r + half * 8);
            const float* rp = residual + m * NDIM + nbase;
            float* op = out + m * NDIM + nbase;
#pragma unroll
            for (int f = 0; f < 8; ++f) {
                const int n = f * 8 + c2;
                float2 res = *(const float2*)(rp + n);
                float2 bz  = *(const float2*)(bias + nbase + n);
                float2 o;
                o.x = acc[mt][f][2 * half]     + bz.x + res.x;
                o.y = acc[mt][f][2 * half + 1] + bz.y + res.y;
                *(float2*)(op + n) = o;
            }
        }
    }
}

// ---------------------------------------------------------------------------
extern "C" void kernel_launch(void* const* d_in, const int* in_sizes, int n_in,
                              void* d_out, int out_size) {
    const float* input    = (const float*)d_in[0];   // [2,4096,4096] f32
    const float* residual = (const float*)d_in[1];   // [2,4096,4096] f32
    const int*   qweight  = (const int*)d_in[2];     // [512,4096] i32
    const float* scales   = (const float*)d_in[3];   // [32,4096] f32
    const int*   qzeros   = (const int*)d_in[4];     // [32,512] i32
    const float* bias     = (const float*)d_in[5];   // [4096] f32
    float* out = (float*)d_out;

    cudaFuncSetAttribute(k_gemm, cudaFuncAttributeMaxDynamicSharedMemorySize,
                         SMEM_DYN);

    k_pre<<<ACONV_BLOCKS + DEQ_BLOCKS, 256>>>(input, qweight, scales, qzeros);

    const int nblocks = (MDIM / TM) * (NDIM / TN);   // 2048
    k_gemm<<<nblocks, 256, SMEM_DYN>>>(residual, bias, out);
}